// round 3
// baseline (speedup 1.0000x reference)
#include <cuda_runtime.h>
#include <cuda_bf16.h>
#include <math.h>

// ---------------- shapes ----------------
#define B_    8
#define L_    1024
#define F_    1024
#define H_    256
#define NH_   8
#define LBL_  4766
#define ROWS_ (B_*L_)      // 8192
#define OH_   (NH_*H_)     // 2048

// ---------------- scratch (device globals; no allocation allowed) ----------------
__device__ float g_x0[ROWS_*F_];     // LN0 output        33.5 MB
__device__ float g_x1[ROWS_*H_];     // after GEMM1+LN1    8 MB
__device__ float g_x2[ROWS_*H_];     // after GEMM2+LN2    8 MB
__device__ float g_att[B_*NH_*L_];   // attention logits/weights
__device__ float g_part[B_*16*NH_*H_]; // pooling partials (deterministic reduction)
__device__ float g_h[B_*OH_];        // pooled [B, NH*H]
__device__ float g_h1[B_*OH_];       // after o_w1 + LN
__device__ float g_p[B_*LBL_];       // sigmoid probs

// ---------------- helpers ----------------
__device__ __forceinline__ float leaky(float v) { return v >= 0.f ? v : 0.01f * v; }

__device__ __forceinline__ void block_reduce2(float& a, float& b, float* s) {
    int t = threadIdx.x;
    s[t] = a; s[256 + t] = b; __syncthreads();
    #pragma unroll
    for (int st = 128; st > 0; st >>= 1) {
        if (t < st) { s[t] += s[t + st]; s[256 + t] += s[256 + t + st]; }
        __syncthreads();
    }
    a = s[0]; b = s[256];
    __syncthreads();
}

// ---------------- LayerNorm over last dim (block per row, 256 threads) ----------------
template<int NF>
__global__ __launch_bounds__(256) void ln_kernel(const float* __restrict__ in,
                                                 float* __restrict__ out,
                                                 const float* __restrict__ g,
                                                 const float* __restrict__ b) {
    constexpr int VPT = NF / 256;
    __shared__ float s[512];
    const float* row = in + (size_t)blockIdx.x * NF;
    float v[VPT];
    float sum = 0.f, sq = 0.f;
    #pragma unroll
    for (int i = 0; i < VPT; i++) {
        v[i] = row[threadIdx.x + i * 256];
        sum += v[i]; sq += v[i] * v[i];
    }
    block_reduce2(sum, sq, s);
    float m   = sum * (1.0f / NF);
    float var = sq  * (1.0f / NF) - m * m;
    float inv = rsqrtf(var + 1e-6f);
    float* orow = out + (size_t)blockIdx.x * NF;
    #pragma unroll
    for (int i = 0; i < VPT; i++) {
        int c = threadIdx.x + i * 256;
        orow[c] = (v[i] - m) * inv * g[c] + b[c];
    }
}

// ---------------- 64x64x16 smem-tiled fp32 GEMM, bias + LeakyReLU epilogue -------------
// C[M,N] = leaky(A[M,K] @ W[K,N] + bias[N]); M%64==0, N%64==0, K%16==0
__global__ __launch_bounds__(256) void gemm_bias_leaky(const float* __restrict__ A,
                                                       const float* __restrict__ W,
                                                       const float* __restrict__ bias,
                                                       float* __restrict__ C,
                                                       int M, int N, int K) {
    __shared__ float As[16][65];   // [k][m], padded against store conflicts
    __shared__ float Bs[16][64];   // [k][n]
    int t  = threadIdx.x;
    int tx = t & 15, ty = t >> 4;
    int bm = blockIdx.x * 64, bn = blockIdx.y * 64;

    float acc[4][4] = {};
    int aRow = t >> 2, aCol = (t & 3) * 4;
    int bRow = t >> 4, bCol = (t & 15) * 4;
    const float* Aptr = A + (size_t)(bm + aRow) * K + aCol;
    const float* Wptr = W + (size_t)bRow * N + bn + bCol;

    for (int k0 = 0; k0 < K; k0 += 16) {
        float4 av = *(const float4*)(Aptr + k0);
        float4 bv = *(const float4*)(Wptr + (size_t)k0 * N);
        As[aCol + 0][aRow] = av.x; As[aCol + 1][aRow] = av.y;
        As[aCol + 2][aRow] = av.z; As[aCol + 3][aRow] = av.w;
        *(float4*)&Bs[bRow][bCol] = bv;
        __syncthreads();
        #pragma unroll
        for (int k = 0; k < 16; k++) {
            float a0 = As[k][ty*4+0], a1 = As[k][ty*4+1];
            float a2 = As[k][ty*4+2], a3 = As[k][ty*4+3];
            float4 b4 = *(const float4*)&Bs[k][tx*4];
            acc[0][0] += a0*b4.x; acc[0][1] += a0*b4.y; acc[0][2] += a0*b4.z; acc[0][3] += a0*b4.w;
            acc[1][0] += a1*b4.x; acc[1][1] += a1*b4.y; acc[1][2] += a1*b4.z; acc[1][3] += a1*b4.w;
            acc[2][0] += a2*b4.x; acc[2][1] += a2*b4.y; acc[2][2] += a2*b4.z; acc[2][3] += a2*b4.w;
            acc[3][0] += a3*b4.x; acc[3][1] += a3*b4.y; acc[3][2] += a3*b4.z; acc[3][3] += a3*b4.w;
        }
        __syncthreads();
    }
    int col = bn + tx * 4;
    float4 bb = *(const float4*)(bias + col);
    #pragma unroll
    for (int i = 0; i < 4; i++) {
        int row = bm + ty * 4 + i;
        float4 o;
        o.x = leaky(acc[i][0] + bb.x);
        o.y = leaky(acc[i][1] + bb.y);
        o.z = leaky(acc[i][2] + bb.z);
        o.w = leaky(acc[i][3] + bb.w);
        *(float4*)(C + (size_t)row * N + col) = o;
    }
}

// ---------------- fused attention scorer: leaky(x@a_w1+b1) -> LN64 -> @a_w2+b2 + mask ----
// 32 rows per block; writes logits in [b][head][l] layout for the softmax.
__global__ __launch_bounds__(256) void attn_kernel(const float* __restrict__ x,
                                                   const float* __restrict__ w1,
                                                   const float* __restrict__ b1,
                                                   const float* __restrict__ lng,
                                                   const float* __restrict__ lnb,
                                                   const float* __restrict__ w2,
                                                   const float* __restrict__ b2,
                                                   const int*  __restrict__ mask,
                                                   float* __restrict__ att) {
    __shared__ float xs[32][256];
    __shared__ float t1[32][64];
    __shared__ float mrow[32], irow[32];
    int t  = threadIdx.x;
    int r0 = blockIdx.x * 32;

    const float4* xsrc = (const float4*)(x + (size_t)r0 * 256);
    float4* xdst = (float4*)&xs[0][0];
    #pragma unroll
    for (int i = 0; i < 8; i++) xdst[t + i * 256] = xsrc[t + i * 256];
    __syncthreads();

    #pragma unroll
    for (int o = 0; o < 8; o++) {
        int idx = o * 256 + t;
        int r = idx >> 6, c = idx & 63;
        float acc = b1[c];
        #pragma unroll 4
        for (int k = 0; k < 256; k++) acc += xs[r][k] * w1[k * 64 + c];
        t1[r][c] = leaky(acc);
    }
    __syncthreads();

    if (t < 32) {
        float s = 0.f, q = 0.f;
        #pragma unroll
        for (int k = 0; k < 64; k++) { float v = t1[t][k]; s += v; q += v * v; }
        float m = s * (1.f / 64.f), var = q * (1.f / 64.f) - m * m;
        mrow[t] = m; irow[t] = rsqrtf(var + 1e-6f);
    }
    __syncthreads();
    #pragma unroll
    for (int o = 0; o < 8; o++) {
        int idx = o * 256 + t;
        int r = idx >> 6, c = idx & 63;
        t1[r][c] = (t1[r][c] - mrow[r]) * irow[r] * lng[c] + lnb[c];
    }
    __syncthreads();

    int r = t >> 3, hd = t & 7;
    float acc = b2[hd];
    #pragma unroll
    for (int k = 0; k < 64; k++) acc += t1[r][k] * w2[k * 8 + hd];
    int gr = r0 + r;
    int b = gr >> 10, l = gr & 1023;
    if (mask[b * 1024 + l] == 0) acc = -1e9f;
    att[((size_t)b * NH_ + hd) * L_ + l] = acc;
}

// ---------------- softmax over L per (b,head) ----------------
__global__ __launch_bounds__(256) void softmax_kernel(float* __restrict__ att) {
    __shared__ float s[256];
    float* row = att + (size_t)blockIdx.x * L_;
    int t = threadIdx.x;
    float v[4]; float mx = -1e30f;
    #pragma unroll
    for (int i = 0; i < 4; i++) { v[i] = row[t + i * 256]; mx = fmaxf(mx, v[i]); }
    s[t] = mx; __syncthreads();
    for (int st = 128; st > 0; st >>= 1) { if (t < st) s[t] = fmaxf(s[t], s[t + st]); __syncthreads(); }
    mx = s[0]; __syncthreads();
    float sum = 0.f;
    #pragma unroll
    for (int i = 0; i < 4; i++) { v[i] = expf(v[i] - mx); sum += v[i]; }
    s[t] = sum; __syncthreads();
    for (int st = 128; st > 0; st >>= 1) { if (t < st) s[t] += s[t + st]; __syncthreads(); }
    float inv = 1.f / s[0];
    #pragma unroll
    for (int i = 0; i < 4; i++) row[t + i * 256] = v[i] * inv;
}

// ---------------- pooling: partial sums over L chunks (deterministic), then reduce ----
__global__ __launch_bounds__(256) void pool_partial(const float* __restrict__ x,
                                                    const float* __restrict__ att,
                                                    float* __restrict__ part) {
    int chunk = blockIdx.x, b = blockIdx.y;
    int t = threadIdx.x;
    __shared__ float as[8][64];
    int l0 = chunk * 64;
    for (int i = t; i < 512; i += 256) {
        int hd = i >> 6, l = i & 63;
        as[hd][l] = att[((size_t)b * NH_ + hd) * L_ + l0 + l];
    }
    __syncthreads();
    float acc[8] = {};
    for (int l = 0; l < 64; l++) {
        float xv = x[((size_t)b * L_ + l0 + l) * H_ + t];
        #pragma unroll
        for (int hd = 0; hd < 8; hd++) acc[hd] += as[hd][l] * xv;
    }
    #pragma unroll
    for (int hd = 0; hd < 8; hd++)
        part[(((size_t)b * 16 + chunk) * NH_ + hd) * H_ + t] = acc[hd];
}

__global__ __launch_bounds__(256) void pool_reduce(const float* __restrict__ part,
                                                   float* __restrict__ h) {
    int hd = blockIdx.x, b = blockIdx.y, t = threadIdx.x;
    float s = 0.f;
    #pragma unroll
    for (int c = 0; c < 16; c++)
        s += part[(((size_t)b * 16 + c) * NH_ + hd) * H_ + t];
    h[(size_t)b * OH_ + hd * H_ + t] = s;
}

// ---------------- M=8 output GEMM 1: leaky(h @ o_w1[2048,2048] + b) ----------------
__global__ __launch_bounds__(256) void out1_kernel(const float* __restrict__ h,
                                                   const float* __restrict__ w,
                                                   const float* __restrict__ bias,
                                                   float* __restrict__ o) {
    __shared__ float hs[8][1024];
    int t = threadIdx.x;
    int j = blockIdx.x * 256 + t;
    float acc[8] = {};
    for (int ch = 0; ch < 2; ch++) {
        __syncthreads();
        for (int i = t; i < 8192; i += 256) {
            int b = i >> 10, k = i & 1023;
            hs[b][k] = h[(size_t)b * OH_ + ch * 1024 + k];
        }
        __syncthreads();
        for (int k = 0; k < 1024; k++) {
            float wv = w[((size_t)(ch * 1024 + k)) * OH_ + j];
            #pragma unroll
            for (int b = 0; b < 8; b++) acc[b] += hs[b][k] * wv;
        }
    }
    float bb = bias[j];
    #pragma unroll
    for (int b = 0; b < 8; b++) o[(size_t)b * OH_ + j] = leaky(acc[b] + bb);
}

// ---------------- M=8 output GEMM 2: sigmoid(h @ o_w2[2048,4766] + b) ----------------
__global__ __launch_bounds__(256) void out2_kernel(const float* __restrict__ h,
                                                   const float* __restrict__ w,
                                                   const float* __restrict__ bias,
                                                   float* __restrict__ p) {
    __shared__ float hs[8][1024];
    int t = threadIdx.x;
    int j = blockIdx.x * 256 + t;
    bool ok = (j < LBL_);
    float acc[8] = {};
    for (int ch = 0; ch < 2; ch++) {
        __syncthreads();
        for (int i = t; i < 8192; i += 256) {
            int b = i >> 10, k = i & 1023;
            hs[b][k] = h[(size_t)b * OH_ + ch * 1024 + k];
        }
        __syncthreads();
        if (ok) {
            for (int k = 0; k < 1024; k++) {
                float wv = w[((size_t)(ch * 1024 + k)) * LBL_ + j];
                #pragma unroll
                for (int b = 0; b < 8; b++) acc[b] += hs[b][k] * wv;
            }
        }
    }
    if (ok) {
        float bb = bias[j];
        #pragma unroll
        for (int b = 0; b < 8; b++) {
            float v = acc[b] + bb;
            p[(size_t)b * LBL_ + j] = 1.f / (1.f + expf(-v));
        }
    }
}

// ---------------- GO max-propagation: out[b,i] = max_j p[b,j]*CM[i,j] --------------
// CM is {0,1}-valued and ~0.2% dense: scan row once, touch p only at nonzeros.
__global__ __launch_bounds__(256) void maxprop_kernel(const float* __restrict__ p,
                                                      const float* __restrict__ CM,
                                                      float* __restrict__ out) {
    int i = blockIdx.x, t = threadIdx.x;
    __shared__ float red[256][9];
    float acc[8] = {};
    const float* row = CM + (size_t)i * LBL_;
    for (int j = t; j < LBL_; j += 256) {
        float c = row[j];
        if (c != 0.f) {
            #pragma unroll
            for (int b = 0; b < 8; b++)
                acc[b] = fmaxf(acc[b], p[(size_t)b * LBL_ + j] * c);
        }
    }
    #pragma unroll
    for (int b = 0; b < 8; b++) red[t][b] = acc[b];
    __syncthreads();
    for (int s = 128; s > 0; s >>= 1) {
        if (t < s) {
            #pragma unroll
            for (int b = 0; b < 8; b++) red[t][b] = fmaxf(red[t][b], red[t + s][b]);
        }
        __syncthreads();
    }
    if (t < 8) out[(size_t)t * LBL_ + i] = red[0][t];
}

// ---------------- launch ----------------
extern "C" void kernel_launch(void* const* d_in, const int* in_sizes, int n_in,
                              void* d_out, int out_size) {
    const float* h_V   = (const float*)d_in[0];
    const int*   mask  = (const int*)  d_in[1];
    const float* ln0_g = (const float*)d_in[2];
    const float* ln0_b = (const float*)d_in[3];
    const float* w_in  = (const float*)d_in[4];
    const float* b_in  = (const float*)d_in[5];
    const float* ln1_g = (const float*)d_in[6];
    const float* ln1_b = (const float*)d_in[7];
    const float* w_h   = (const float*)d_in[8];
    const float* b_h   = (const float*)d_in[9];
    const float* ln2_g = (const float*)d_in[10];
    const float* ln2_b = (const float*)d_in[11];
    const float* a_w1  = (const float*)d_in[12];
    const float* a_b1  = (const float*)d_in[13];
    const float* a_lng = (const float*)d_in[14];
    const float* a_lnb = (const float*)d_in[15];
    const float* a_w2  = (const float*)d_in[16];
    const float* a_b2  = (const float*)d_in[17];
    const float* o_w1  = (const float*)d_in[18];
    const float* o_b1  = (const float*)d_in[19];
    const float* o_lng = (const float*)d_in[20];
    const float* o_lnb = (const float*)d_in[21];
    const float* o_w2  = (const float*)d_in[22];
    const float* o_b2  = (const float*)d_in[23];
    const float* CM    = (const float*)d_in[24];
    float* out = (float*)d_out;

    float *x0, *x1, *x2, *att, *part, *hb, *h1, *p;
    cudaGetSymbolAddress((void**)&x0,   g_x0);
    cudaGetSymbolAddress((void**)&x1,   g_x1);
    cudaGetSymbolAddress((void**)&x2,   g_x2);
    cudaGetSymbolAddress((void**)&att,  g_att);
    cudaGetSymbolAddress((void**)&part, g_part);
    cudaGetSymbolAddress((void**)&hb,   g_h);
    cudaGetSymbolAddress((void**)&h1,   g_h1);
    cudaGetSymbolAddress((void**)&p,    g_p);

    // input + hidden blocks
    ln_kernel<1024><<<ROWS_, 256>>>(h_V, x0, ln0_g, ln0_b);
    gemm_bias_leaky<<<dim3(ROWS_/64, H_/64), 256>>>(x0, w_in, b_in, x1, ROWS_, H_, F_);
    ln_kernel<256><<<ROWS_, 256>>>(x1, x1, ln1_g, ln1_b);
    gemm_bias_leaky<<<dim3(ROWS_/64, H_/64), 256>>>(x1, w_h, b_h, x2, ROWS_, H_, H_);
    ln_kernel<256><<<ROWS_, 256>>>(x2, x2, ln2_g, ln2_b);

    // attention pooling
    attn_kernel<<<ROWS_/32, 256>>>(x2, a_w1, a_b1, a_lng, a_lnb, a_w2, a_b2, mask, att);
    softmax_kernel<<<B_*NH_, 256>>>(att);
    pool_partial<<<dim3(16, B_), 256>>>(x2, att, part);
    pool_reduce<<<dim3(NH_, B_), 256>>>(part, hb);

    // output block
    out1_kernel<<<OH_/256, 256>>>(hb, o_w1, o_b1, h1);
    ln_kernel<2048><<<B_, 256>>>(h1, h1, o_lng, o_lnb);
    out2_kernel<<<(LBL_ + 255)/256, 256>>>(h1, o_w2, o_b2, p);

    // GO hierarchy max-product
    maxprop_kernel<<<LBL_, 256>>>(p, CM, out);
}

// round 4
// speedup vs baseline: 2.2959x; 2.2959x over previous
#include <cuda_runtime.h>
#include <cuda_bf16.h>
#include <math.h>

// ---------------- shapes ----------------
#define B_    8
#define L_    1024
#define F_    1024
#define H_    256
#define NH_   8
#define LBL_  4766
#define ROWS_ (B_*L_)      // 8192
#define OH_   (NH_*H_)     // 2048

// ---------------- scratch (device globals; no allocation allowed) ----------------
__device__ float g_x1[ROWS_*H_];       // after GEMM1 (leaky, pre-LN1)
__device__ float g_x2[ROWS_*H_];       // after GEMM2 (+LN2 in place)
__device__ float g_stats[ROWS_*2];     // per-row (mean, inv) for fused LN
__device__ float g_att[B_*NH_*L_];     // attention logits/weights
__device__ float g_part[B_*16*NH_*H_]; // pooling partials
__device__ float g_h[B_*OH_];          // pooled [B, NH*H]
__device__ float g_h1[B_*OH_];         // after o_w1 + LN
__device__ float g_p[B_*LBL_];         // sigmoid probs
__device__ float g_op1[16*8*OH_];      // split-K partials, out GEMM 1
__device__ float g_op2[16*8*LBL_];     // split-K partials, out GEMM 2

// ---------------- helpers ----------------
__device__ __forceinline__ float leaky(float v) { return v >= 0.f ? v : 0.01f * v; }

__device__ __forceinline__ void block_reduce2(float& a, float& b, float* s) {
    int t = threadIdx.x;
    s[t] = a; s[256 + t] = b; __syncthreads();
    #pragma unroll
    for (int st = 128; st > 0; st >>= 1) {
        if (t < st) { s[t] += s[t + st]; s[256 + t] += s[256 + t + st]; }
        __syncthreads();
    }
    a = s[0]; b = s[256];
    __syncthreads();
}

// ---------------- per-row LN stats: (mean, rsqrt(var+eps)) ----------------
template<int NF>
__global__ __launch_bounds__(256) void rowstat_kernel(const float* __restrict__ in,
                                                      float* __restrict__ stats) {
    constexpr int VPT = NF / 256;
    __shared__ float s[512];
    const float* row = in + (size_t)blockIdx.x * NF;
    float sum = 0.f, sq = 0.f;
    #pragma unroll
    for (int i = 0; i < VPT; i++) {
        float v = row[threadIdx.x + i * 256];
        sum += v; sq += v * v;
    }
    block_reduce2(sum, sq, s);
    if (threadIdx.x == 0) {
        float m   = sum * (1.0f / NF);
        float var = sq  * (1.0f / NF) - m * m;
        stats[2 * blockIdx.x]     = m;
        stats[2 * blockIdx.x + 1] = rsqrtf(var + 1e-6f);
    }
}

// ---------------- full LayerNorm (in-place safe) ----------------
template<int NF>
__global__ __launch_bounds__(256) void ln_kernel(const float* __restrict__ in,
                                                 float* __restrict__ out,
                                                 const float* __restrict__ g,
                                                 const float* __restrict__ b) {
    constexpr int VPT = NF / 256;
    __shared__ float s[512];
    const float* row = in + (size_t)blockIdx.x * NF;
    float v[VPT];
    float sum = 0.f, sq = 0.f;
    #pragma unroll
    for (int i = 0; i < VPT; i++) {
        v[i] = row[threadIdx.x + i * 256];
        sum += v[i]; sq += v[i] * v[i];
    }
    block_reduce2(sum, sq, s);
    float m   = sum * (1.0f / NF);
    float var = sq  * (1.0f / NF) - m * m;
    float inv = rsqrtf(var + 1e-6f);
    float* orow = out + (size_t)blockIdx.x * NF;
    #pragma unroll
    for (int i = 0; i < VPT; i++) {
        int c = threadIdx.x + i * 256;
        orow[c] = (v[i] - m) * inv * g[c] + b[c];
    }
}

// ---------------- 128x128x16 double-buffered fp32 GEMM -----------------------
// C = leaky( LN?(A) @ W + bias ).  If FUSE: A element a=(raw-m)*inv*lg[k]+lb[k]
// with per-row (m,inv) from stats. M%128==0, N%128==0, K%16==0.
template<bool FUSE>
__global__ __launch_bounds__(256) void gemm128(const float* __restrict__ A,
                                               const float* __restrict__ stats,
                                               const float* __restrict__ lg,
                                               const float* __restrict__ lb,
                                               const float* __restrict__ W,
                                               const float* __restrict__ bias,
                                               float* __restrict__ C,
                                               int M, int N, int K) {
    __shared__ float As[2][16][132];   // [k][m], transposed, padded
    __shared__ float Bs[2][16][128];   // [k][n]
    int t  = threadIdx.x;
    int bm = blockIdx.x * 128, bn = blockIdx.y * 128;
    int ar = t >> 1, ak = (t & 1) * 8;       // A load: row, k-base (8 k's)
    int bk = t >> 4, bnn = (t & 15) * 8;     // B load: k-row, n-base (8 n's)
    int tx = t & 15, ty = t >> 4;            // compute: 8 cols, 8 rows

    float m = 0.f, inv = 0.f;
    if (FUSE) { m = stats[2 * (bm + ar)]; inv = stats[2 * (bm + ar) + 1]; }

    const float* Ap = A + (size_t)(bm + ar) * K + ak;
    const float* Wp = W + (size_t)bk * N + bn + bnn;

    float acc[8][8] = {};
    float4 ra0, ra1, rb0, rb1;

    auto gload = [&](int k0) {
        ra0 = *(const float4*)(Ap + k0);
        ra1 = *(const float4*)(Ap + k0 + 4);
        if (FUSE) {
            float4 g0 = *(const float4*)(lg + k0 + ak);
            float4 g1 = *(const float4*)(lg + k0 + ak + 4);
            float4 c0 = *(const float4*)(lb + k0 + ak);
            float4 c1 = *(const float4*)(lb + k0 + ak + 4);
            ra0.x = (ra0.x - m) * inv * g0.x + c0.x;
            ra0.y = (ra0.y - m) * inv * g0.y + c0.y;
            ra0.z = (ra0.z - m) * inv * g0.z + c0.z;
            ra0.w = (ra0.w - m) * inv * g0.w + c0.w;
            ra1.x = (ra1.x - m) * inv * g1.x + c1.x;
            ra1.y = (ra1.y - m) * inv * g1.y + c1.y;
            ra1.z = (ra1.z - m) * inv * g1.z + c1.z;
            ra1.w = (ra1.w - m) * inv * g1.w + c1.w;
        }
        rb0 = *(const float4*)(Wp + (size_t)k0 * N);
        rb1 = *(const float4*)(Wp + (size_t)k0 * N + 4);
    };
    auto sstore = [&](int buf) {
        As[buf][ak + 0][ar] = ra0.x; As[buf][ak + 1][ar] = ra0.y;
        As[buf][ak + 2][ar] = ra0.z; As[buf][ak + 3][ar] = ra0.w;
        As[buf][ak + 4][ar] = ra1.x; As[buf][ak + 5][ar] = ra1.y;
        As[buf][ak + 6][ar] = ra1.z; As[buf][ak + 7][ar] = ra1.w;
        *(float4*)&Bs[buf][bk][bnn]     = rb0;
        *(float4*)&Bs[buf][bk][bnn + 4] = rb1;
    };

    gload(0);
    sstore(0);
    __syncthreads();

    int nst = K / 16;
    for (int s = 0; s < nst; s++) {
        int buf = s & 1;
        if (s + 1 < nst) gload((s + 1) * 16);
        #pragma unroll
        for (int k = 0; k < 16; k++) {
            float4 a0 = *(const float4*)&As[buf][k][ty * 8];
            float4 a1 = *(const float4*)&As[buf][k][ty * 8 + 4];
            float4 b0 = *(const float4*)&Bs[buf][k][tx * 8];
            float4 b1 = *(const float4*)&Bs[buf][k][tx * 8 + 4];
            float av[8] = {a0.x, a0.y, a0.z, a0.w, a1.x, a1.y, a1.z, a1.w};
            float bv[8] = {b0.x, b0.y, b0.z, b0.w, b1.x, b1.y, b1.z, b1.w};
            #pragma unroll
            for (int i = 0; i < 8; i++)
                #pragma unroll
                for (int j = 0; j < 8; j++)
                    acc[i][j] += av[i] * bv[j];
        }
        if (s + 1 < nst) {
            sstore(buf ^ 1);
            __syncthreads();
        }
    }

    int col0 = bn + tx * 8;
    float4 bb0 = *(const float4*)(bias + col0);
    float4 bb1 = *(const float4*)(bias + col0 + 4);
    #pragma unroll
    for (int i = 0; i < 8; i++) {
        int row = bm + ty * 8 + i;
        float4 o0, o1;
        o0.x = leaky(acc[i][0] + bb0.x); o0.y = leaky(acc[i][1] + bb0.y);
        o0.z = leaky(acc[i][2] + bb0.z); o0.w = leaky(acc[i][3] + bb0.w);
        o1.x = leaky(acc[i][4] + bb1.x); o1.y = leaky(acc[i][5] + bb1.y);
        o1.z = leaky(acc[i][6] + bb1.z); o1.w = leaky(acc[i][7] + bb1.w);
        *(float4*)(C + (size_t)row * N + col0)     = o0;
        *(float4*)(C + (size_t)row * N + col0 + 4) = o1;
    }
}

// ---------------- fused attention scorer ----------------
__global__ __launch_bounds__(256) void attn_kernel(const float* __restrict__ x,
                                                   const float* __restrict__ w1,
                                                   const float* __restrict__ b1,
                                                   const float* __restrict__ lng,
                                                   const float* __restrict__ lnb,
                                                   const float* __restrict__ w2,
                                                   const float* __restrict__ b2,
                                                   const int*  __restrict__ mask,
                                                   float* __restrict__ att) {
    __shared__ float xs[32][256];
    __shared__ float t1[32][64];
    __shared__ float mrow[32], irow[32];
    int t  = threadIdx.x;
    int r0 = blockIdx.x * 32;

    const float4* xsrc = (const float4*)(x + (size_t)r0 * 256);
    float4* xdst = (float4*)&xs[0][0];
    #pragma unroll
    for (int i = 0; i < 8; i++) xdst[t + i * 256] = xsrc[t + i * 256];
    __syncthreads();

    #pragma unroll
    for (int o = 0; o < 8; o++) {
        int idx = o * 256 + t;
        int r = idx >> 6, c = idx & 63;
        float acc = b1[c];
        #pragma unroll 4
        for (int k = 0; k < 256; k++) acc += xs[r][k] * w1[k * 64 + c];
        t1[r][c] = leaky(acc);
    }
    __syncthreads();

    if (t < 32) {
        float s = 0.f, q = 0.f;
        #pragma unroll
        for (int k = 0; k < 64; k++) { float v = t1[t][k]; s += v; q += v * v; }
        float m = s * (1.f / 64.f), var = q * (1.f / 64.f) - m * m;
        mrow[t] = m; irow[t] = rsqrtf(var + 1e-6f);
    }
    __syncthreads();
    #pragma unroll
    for (int o = 0; o < 8; o++) {
        int idx = o * 256 + t;
        int r = idx >> 6, c = idx & 63;
        t1[r][c] = (t1[r][c] - mrow[r]) * irow[r] * lng[c] + lnb[c];
    }
    __syncthreads();

    int r = t >> 3, hd = t & 7;
    float acc = b2[hd];
    #pragma unroll
    for (int k = 0; k < 64; k++) acc += t1[r][k] * w2[k * 8 + hd];
    int gr = r0 + r;
    int b = gr >> 10, l = gr & 1023;
    if (mask[b * 1024 + l] == 0) acc = -1e9f;
    att[((size_t)b * NH_ + hd) * L_ + l] = acc;
}

// ---------------- softmax over L per (b,head) ----------------
__global__ __launch_bounds__(256) void softmax_kernel(float* __restrict__ att) {
    __shared__ float s[256];
    float* row = att + (size_t)blockIdx.x * L_;
    int t = threadIdx.x;
    float v[4]; float mx = -1e30f;
    #pragma unroll
    for (int i = 0; i < 4; i++) { v[i] = row[t + i * 256]; mx = fmaxf(mx, v[i]); }
    s[t] = mx; __syncthreads();
    for (int st = 128; st > 0; st >>= 1) { if (t < st) s[t] = fmaxf(s[t], s[t + st]); __syncthreads(); }
    mx = s[0]; __syncthreads();
    float sum = 0.f;
    #pragma unroll
    for (int i = 0; i < 4; i++) { v[i] = expf(v[i] - mx); sum += v[i]; }
    s[t] = sum; __syncthreads();
    for (int st = 128; st > 0; st >>= 1) { if (t < st) s[t] += s[t + st]; __syncthreads(); }
    float inv = 1.f / s[0];
    #pragma unroll
    for (int i = 0; i < 4; i++) row[t + i * 256] = v[i] * inv;
}

// ---------------- pooling: deterministic partial sums + reduce ----------------
__global__ __launch_bounds__(256) void pool_partial(const float* __restrict__ x,
                                                    const float* __restrict__ att,
                                                    float* __restrict__ part) {
    int chunk = blockIdx.x, b = blockIdx.y;
    int t = threadIdx.x;
    __shared__ float as[8][64];
    int l0 = chunk * 64;
    for (int i = t; i < 512; i += 256) {
        int hd = i >> 6, l = i & 63;
        as[hd][l] = att[((size_t)b * NH_ + hd) * L_ + l0 + l];
    }
    __syncthreads();
    float acc[8] = {};
    for (int l = 0; l < 64; l++) {
        float xv = x[((size_t)b * L_ + l0 + l) * H_ + t];
        #pragma unroll
        for (int hd = 0; hd < 8; hd++) acc[hd] += as[hd][l] * xv;
    }
    #pragma unroll
    for (int hd = 0; hd < 8; hd++)
        part[(((size_t)b * 16 + chunk) * NH_ + hd) * H_ + t] = acc[hd];
}

__global__ __launch_bounds__(256) void pool_reduce(const float* __restrict__ part,
                                                   float* __restrict__ h) {
    int hd = blockIdx.x, b = blockIdx.y, t = threadIdx.x;
    float s = 0.f;
    #pragma unroll
    for (int c = 0; c < 16; c++)
        s += part[(((size_t)b * 16 + c) * NH_ + hd) * H_ + t];
    h[(size_t)b * OH_ + hd * H_ + t] = s;
}

// ---------------- M=8 output GEMM: split-K partials ----------------
// grid = (ceil(N/256), 16). block (bx,ks): cols bx*256..+255, k in [ks*128, +128)
__global__ __launch_bounds__(256) void out_partial(const float* __restrict__ h,
                                                   const float* __restrict__ w,
                                                   float* __restrict__ part, int N) {
    __shared__ float hs[8][128];
    int t = threadIdx.x;
    int j = blockIdx.x * 256 + t;
    int k0 = blockIdx.y * 128;
    for (int i = t; i < 1024; i += 256)
        hs[i >> 7][i & 127] = h[(size_t)(i >> 7) * OH_ + k0 + (i & 127)];
    __syncthreads();
    if (j >= N) return;
    float acc[8] = {};
    const float* wp = w + (size_t)k0 * N + j;
    #pragma unroll 8
    for (int kk = 0; kk < 128; kk++) {
        float wv = wp[(size_t)kk * N];
        #pragma unroll
        for (int b = 0; b < 8; b++) acc[b] += hs[b][kk] * wv;
    }
    float* pp = part + (size_t)(blockIdx.y * 8) * N + j;
    #pragma unroll
    for (int b = 0; b < 8; b++) pp[(size_t)b * N] = acc[b];
}

// MODE 0: leaky, MODE 1: sigmoid
template<int MODE>
__global__ __launch_bounds__(256) void out_reduce(const float* __restrict__ part,
                                                  const float* __restrict__ bias,
                                                  float* __restrict__ o, int N) {
    int j = blockIdx.x * 256 + threadIdx.x;
    if (j >= N) return;
    float s[8] = {};
    #pragma unroll
    for (int ks = 0; ks < 16; ks++)
        #pragma unroll
        for (int b = 0; b < 8; b++)
            s[b] += part[(size_t)(ks * 8 + b) * N + j];
    float bb = bias[j];
    #pragma unroll
    for (int b = 0; b < 8; b++) {
        float v = s[b] + bb;
        o[(size_t)b * N + j] = MODE ? (1.f / (1.f + expf(-v))) : leaky(v);
    }
}

// ---------------- GO max-propagation ----------------
__global__ __launch_bounds__(256) void maxprop_kernel(const float* __restrict__ p,
                                                      const float* __restrict__ CM,
                                                      float* __restrict__ out) {
    int i = blockIdx.x, t = threadIdx.x;
    __shared__ float red[256][9];
    float acc[8] = {};
    const float* row = CM + (size_t)i * LBL_;
    for (int j = t; j < LBL_; j += 256) {
        float c = row[j];
        if (c != 0.f) {
            #pragma unroll
            for (int b = 0; b < 8; b++)
                acc[b] = fmaxf(acc[b], p[(size_t)b * LBL_ + j] * c);
        }
    }
    #pragma unroll
    for (int b = 0; b < 8; b++) red[t][b] = acc[b];
    __syncthreads();
    for (int s = 128; s > 0; s >>= 1) {
        if (t < s) {
            #pragma unroll
            for (int b = 0; b < 8; b++) red[t][b] = fmaxf(red[t][b], red[t + s][b]);
        }
        __syncthreads();
    }
    if (t < 8) out[(size_t)t * LBL_ + i] = red[0][t];
}

// ---------------- launch ----------------
extern "C" void kernel_launch(void* const* d_in, const int* in_sizes, int n_in,
                              void* d_out, int out_size) {
    const float* h_V   = (const float*)d_in[0];
    const int*   mask  = (const int*)  d_in[1];
    const float* ln0_g = (const float*)d_in[2];
    const float* ln0_b = (const float*)d_in[3];
    const float* w_in  = (const float*)d_in[4];
    const float* b_in  = (const float*)d_in[5];
    const float* ln1_g = (const float*)d_in[6];
    const float* ln1_b = (const float*)d_in[7];
    const float* w_h   = (const float*)d_in[8];
    const float* b_h   = (const float*)d_in[9];
    const float* ln2_g = (const float*)d_in[10];
    const float* ln2_b = (const float*)d_in[11];
    const float* a_w1  = (const float*)d_in[12];
    const float* a_b1  = (const float*)d_in[13];
    const float* a_lng = (const float*)d_in[14];
    const float* a_lnb = (const float*)d_in[15];
    const float* a_w2  = (const float*)d_in[16];
    const float* a_b2  = (const float*)d_in[17];
    const float* o_w1  = (const float*)d_in[18];
    const float* o_b1  = (const float*)d_in[19];
    const float* o_lng = (const float*)d_in[20];
    const float* o_lnb = (const float*)d_in[21];
    const float* o_w2  = (const float*)d_in[22];
    const float* o_b2  = (const float*)d_in[23];
    const float* CM    = (const float*)d_in[24];
    float* out = (float*)d_out;

    float *x1, *x2, *stats, *att, *part, *hb, *h1, *p, *op1, *op2;
    cudaGetSymbolAddress((void**)&x1,    g_x1);
    cudaGetSymbolAddress((void**)&x2,    g_x2);
    cudaGetSymbolAddress((void**)&stats, g_stats);
    cudaGetSymbolAddress((void**)&att,   g_att);
    cudaGetSymbolAddress((void**)&part,  g_part);
    cudaGetSymbolAddress((void**)&hb,    g_h);
    cudaGetSymbolAddress((void**)&h1,    g_h1);
    cudaGetSymbolAddress((void**)&p,     g_p);
    cudaGetSymbolAddress((void**)&op1,   g_op1);
    cudaGetSymbolAddress((void**)&op2,   g_op2);

    // input block: LN0 fused into GEMM1 via row stats
    rowstat_kernel<1024><<<ROWS_, 256>>>(h_V, stats);
    gemm128<true><<<dim3(ROWS_/128, H_/128), 256>>>(h_V, stats, ln0_g, ln0_b,
                                                    w_in, b_in, x1, ROWS_, H_, F_);
    // hidden block: LN1 fused into GEMM2
    rowstat_kernel<256><<<ROWS_, 256>>>(x1, stats);
    gemm128<true><<<dim3(ROWS_/128, H_/128), 256>>>(x1, stats, ln1_g, ln1_b,
                                                    w_h, b_h, x2, ROWS_, H_, H_);
    ln_kernel<256><<<ROWS_, 256>>>(x2, x2, ln2_g, ln2_b);

    // attention pooling
    attn_kernel<<<ROWS_/32, 256>>>(x2, a_w1, a_b1, a_lng, a_lnb, a_w2, a_b2, mask, att);
    softmax_kernel<<<B_*NH_, 256>>>(att);
    pool_partial<<<dim3(16, B_), 256>>>(x2, att, part);
    pool_reduce<<<dim3(NH_, B_), 256>>>(part, hb);

    // output block (split-K, deterministic two-phase)
    out_partial<<<dim3(OH_/256, 16), 256>>>(hb, o_w1, op1, OH_);
    out_reduce<0><<<OH_/256, 256>>>(op1, o_b1, h1, OH_);
    ln_kernel<2048><<<B_, 256>>>(h1, h1, o_lng, o_lnb);
    out_partial<<<dim3((LBL_+255)/256, 16), 256>>>(h1, o_w2, op2, LBL_);
    out_reduce<1><<<(LBL_+255)/256, 256>>>(op2, o_b2, p, LBL_);

    // GO hierarchy max-product
    maxprop_kernel<<<LBL_, 256>>>(p, CM, out);
}